// round 14
// baseline (speedup 1.0000x reference)
#include <cuda_runtime.h>
#include <cuda_bf16.h>
#include <math.h>
#include <cstdint>

#define D      13
#define NPIX   1024
#define BATCH  32
#define TSTEPS 24
#define NCL    8
#define NKT    8        // key tiles of 128

typedef unsigned long long u64;

// ---------------- f32x2 helpers (conv path) ----------------
__device__ __forceinline__ u64 fma2(u64 a, u64 b, u64 c) {
    u64 d; asm("fma.rn.f32x2 %0, %1, %2, %3;" : "=l"(d) : "l"(a), "l"(b), "l"(c)); return d;
}
__device__ __forceinline__ u64 pack2(float lo, float hi) {
    u64 d; asm("mov.b64 %0, {%1, %2};" : "=l"(d) : "f"(lo), "f"(hi)); return d;
}
__device__ __forceinline__ void unpack2(u64 v, float& lo, float& hi) {
    asm("mov.b64 {%0, %1}, %2;" : "=f"(lo), "=f"(hi) : "l"(v));
}
__device__ __forceinline__ float ex2f(float x) {
    float r; asm("ex2.approx.f32 %0, %1;" : "=f"(r) : "f"(x)); return r;
}

// ---------------- MMA helpers (sm_80+ PTX, no arch-gated features) ----------------
__device__ __forceinline__ uint32_t smem_u32(const void* p) {
    uint32_t a; asm("{ .reg .u64 t; cvta.to.shared.u64 t, %1; cvt.u32.u64 %0, t; }" : "=r"(a) : "l"(p));
    return a;
}
__device__ __forceinline__ void bfsplit(float x, unsigned short& h, unsigned short& l) {
    asm("cvt.rn.bf16.f32 %0, %1;" : "=h"(h) : "f"(x));
    float hf = __uint_as_float(((unsigned)h) << 16);
    float r = x - hf;
    asm("cvt.rn.bf16.f32 %0, %1;" : "=h"(l) : "f"(r));
}
__device__ __forceinline__ unsigned short bf16of(float x) {
    unsigned short h; asm("cvt.rn.bf16.f32 %0, %1;" : "=h"(h) : "f"(x)); return h;
}
__device__ __forceinline__ uint32_t bf16pair(float lo, float hi) {
    uint32_t r; asm("cvt.rn.bf16x2.f32 %0, %1, %2;" : "=r"(r) : "f"(hi), "f"(lo)); return r;
}
#define MMA_BF16(dd, a, b) \
    asm volatile("mma.sync.aligned.m16n8k16.row.col.f32.bf16.bf16.f32 " \
        "{%0,%1,%2,%3}, {%4,%5,%6,%7}, {%8,%9}, {%0,%1,%2,%3};" \
        : "+f"((dd)[0]),"+f"((dd)[1]),"+f"((dd)[2]),"+f"((dd)[3]) \
        : "r"((a)[0]),"r"((a)[1]),"r"((a)[2]),"r"((a)[3]), "r"((b)[0]),"r"((b)[1]))
#define LDM_X4(r, addr) \
    asm volatile("ldmatrix.sync.aligned.m8n8.x4.shared.b16 {%0,%1,%2,%3}, [%4];" \
        : "=r"((r)[0]),"=r"((r)[1]),"=r"((r)[2]),"=r"((r)[3]) : "r"(addr))

// ---------------- persistent state ----------------
__device__ float g_c   [BATCH*D*NPIX];
__device__ float g_h   [BATCH*D*NPIX];
__device__ float g_m   [BATCH*D*NPIX];
__device__ float g_htmp[BATCH*D*NPIX];
__device__ float g_q   [BATCH*D*NPIX];   // pre-scaled by log2(e)
__device__ float g_kh  [BATCH*D*NPIX];
__device__ float g_vh  [BATCH*D*NPIX];
__device__ float g_km  [BATCH*D*NPIX];
__device__ float g_vm  [BATCH*D*NPIX];

__global__ void zero_state() {
    int total = BATCH*D*NPIX;
    for (int i = blockIdx.x*blockDim.x + threadIdx.x; i < total; i += gridDim.x*blockDim.x) {
        g_c[i] = 0.f; g_h[i] = 0.f; g_m[i] = 0.f;
    }
}

// ---------------- conv weight pre-pack ----------------
#define CONV_WP (13*26*9)
__device__ u64 g_wif[CONV_WP];
__device__ u64 g_wgo[CONV_WP];

__global__ void pack_conv_weights(const float* __restrict__ Wg) {
    int i = blockIdx.x*256 + threadIdx.x;
    if (i < CONV_WP) {
        int d = i / 234, r = i % 234;
        g_wif[i] = pack2(Wg[(     d)*234 + r], Wg[(13 + d)*234 + r]);
        g_wgo[i] = pack2(Wg[(26 + d)*234 + r], Wg[(39 + d)*234 + r]);
    }
}

// ---------------- ConvLSTM step + fused SAM projections (unchanged) ----------------
#define CONV_TILE_F2 (26*6*34)
#define PROJ_W_F     (5*169)
#define CONV_SMEM5   (2*CONV_WP*8 + CONV_TILE_F2*4 + PROJ_W_F*4 + 13*128*4)

__global__ void __launch_bounds__(256) conv_lstm_proj(
        const float* __restrict__ x1, int t,
        const float* __restrict__ Wq,  const float* __restrict__ Wkh,
        const float* __restrict__ Wvh, const float* __restrict__ Wkm,
        const float* __restrict__ Wvm) {
    extern __shared__ char smraw[];
    u64*   swif = (u64*)smraw;
    u64*   swgo = swif + CONV_WP;
    float* st   = (float*)(swgo + CONV_WP);
    float* spw  = st + CONV_TILE_F2;
    float* sht  = spw + PROJ_W_F;

    int b  = blockIdx.y;
    int y0 = blockIdx.x * 4;

    const ulonglong2* gi = (const ulonglong2*)g_wif;
    const ulonglong2* go = (const ulonglong2*)g_wgo;
    ulonglong2* si = (ulonglong2*)swif;
    ulonglong2* so = (ulonglong2*)swgo;
    for (int i = threadIdx.x; i < CONV_WP/2; i += 256) { si[i] = gi[i]; so[i] = go[i]; }
    if (threadIdx.x == 0) { swif[CONV_WP-1] = g_wif[CONV_WP-1]; swgo[CONV_WP-1] = g_wgo[CONV_WP-1]; }
    for (int i = threadIdx.x; i < PROJ_W_F; i += 256) {
        spw[i] = (i < 169) ? Wq[i] : (i < 338) ? Wkh[i-169] : (i < 507) ? Wvh[i-338]
               : (i < 676) ? Wkm[i-507] : Wvm[i-676];
    }
    for (int i = threadIdx.x; i < CONV_TILE_F2; i += 256) {
        int ci = i / 204; int rem = i % 204; int rr = rem / 34; int cc = rem % 34;
        int y = y0 + rr - 1, x = cc - 1;
        float v = 0.f;
        if ((unsigned)y < 32u && (unsigned)x < 32u) {
            int n = y*32 + x;
            v = (ci < 13) ? x1[(((size_t)b*TSTEPS + t)*D + ci)*NPIX + n]
                          : g_h[((size_t)b*D + (ci-13))*NPIX + n];
        }
        st[i] = v;
    }
    __syncthreads();

    int px  = threadIdx.x & 127;
    int grp = threadIdx.x >> 7;
    int r = px >> 5, c = px & 31;
    int n = (y0 + r)*32 + c;
    int d0 = grp * 7;
    int nd = grp ? 6 : 7;

    u64 aif[7], ago[7];
    #pragma unroll
    for (int dd = 0; dd < 7; dd++) { aif[dd] = 0ull; ago[dd] = 0ull; }

    for (int ci = 0; ci < 26; ci++) {
        const float* tb = st + ci*204 + r*34 + c;
        #pragma unroll
        for (int ky = 0; ky < 3; ky++) {
            #pragma unroll
            for (int kx = 0; kx < 3; kx++) {
                float v = tb[ky*34 + kx];
                u64 vv = pack2(v, v);
                int rt = ci*9 + ky*3 + kx;
                #pragma unroll
                for (int dd = 0; dd < 7; dd++) {
                    if (dd < nd) {
                        aif[dd] = fma2(swif[(d0+dd)*234 + rt], vv, aif[dd]);
                        ago[dd] = fma2(swgo[(d0+dd)*234 + rt], vv, ago[dd]);
                    }
                }
            }
        }
    }

    #pragma unroll
    for (int dd = 0; dd < 7; dd++) {
        if (dd < nd) {
            int d = d0 + dd;
            float ai, af, ag, ao;
            unpack2(aif[dd], ai, af);
            unpack2(ago[dd], ag, ao);
            float ig = 1.f/(1.f + __expf(-ai));
            float fg = 1.f/(1.f + __expf(-af));
            float og = 1.f/(1.f + __expf(-ao));
            float gg = tanhf(ag);
            size_t idx = ((size_t)b*D + d)*NPIX + n;
            float cn = fg*g_c[idx] + ig*gg;
            g_c[idx] = cn;
            float htv = og*tanhf(cn);
            g_htmp[idx] = htv;
            sht[d*128 + px] = htv;
        }
    }
    __syncthreads();

    const float L2E = 1.44269504f;
    size_t pb = (size_t)b*D*NPIX + n;
    if (grp == 0) {
        float ht[D];
        #pragma unroll
        for (int d = 0; d < D; d++) ht[d] = sht[d*128 + px];
        #pragma unroll
        for (int o = 0; o < D; o++) {
            float q = 0.f, kh = 0.f;
            #pragma unroll
            for (int d = 0; d < D; d++) {
                q  = fmaf(spw[      o*13 + d], ht[d], q);
                kh = fmaf(spw[169 + o*13 + d], ht[d], kh);
            }
            g_q [pb + (size_t)o*NPIX] = q*L2E;
            g_kh[pb + (size_t)o*NPIX] = kh;
        }
    } else {
        float ht[D], mv[D];
        #pragma unroll
        for (int d = 0; d < D; d++) {
            ht[d] = sht[d*128 + px];
            mv[d] = g_m[((size_t)b*D + d)*NPIX + n];
        }
        #pragma unroll
        for (int o = 0; o < D; o++) {
            float vh = 0.f, km = 0.f, vm = 0.f;
            #pragma unroll
            for (int d = 0; d < D; d++) {
                vh = fmaf(spw[338 + o*13 + d], ht[d], vh);
                km = fmaf(spw[507 + o*13 + d], mv[d], km);
                vm = fmaf(spw[676 + o*13 + d], mv[d], vm);
            }
            g_vh[pb + (size_t)o*NPIX] = vh;
            g_km[pb + (size_t)o*NPIX] = km;
            g_vm[pb + (size_t)o*NPIX] = vm;
        }
    }
}

// ---------------- fused warp-MMA flash attention + SAM post ----------------
#define KSTR 24
#define VSTR 136
#define VROWS 16
#define BUFH (2*128*KSTR + VROWS*VSTR)   // 8320 halves per buffer
#define OFF_KLO (128*KSTR)
#define OFF_V   (2*128*KSTR)
#define ZBUF_F  (2*14*128)
// dynamic smem layout: smb halves [2*BUFH] | zbuf f32 [2*14*128] | swz [338] | swm [1014]
#define ATTN_SMEM (2*BUFH*2 + ZBUF_F*4 + 338*4 + 1014*4)

__global__ void __launch_bounds__(256, 2) sam_attn_post(
        const float* __restrict__ Wz, const float* __restrict__ Wm) {
    extern __shared__ char dsm[];
    unsigned short* smb = (unsigned short*)dsm;
    float* zbuf = (float*)(dsm + 2*BUFH*2);
    float* swz  = zbuf + ZBUF_F;
    float* swm  = swz + 338;

    int tid = threadIdx.x;
    int w    = tid >> 5;
    int lane = tid & 31;
    int g = lane >> 2, t = lane & 3;
    int grp = lane >> 3, rr = lane & 7;

    int qt = blockIdx.x;          // 8 tiles of 128 queries
    int b  = blockIdx.y;

    const float* Qp = g_q + (size_t)b*D*NPIX;

    // weight + pad init
    for (int i = tid; i < 338; i += 256) swz[i] = Wz[i];
    for (int i = tid; i < 1014; i += 256) swm[i] = Wm[i];
    for (int i = tid; i < 2*BUFH; i += 256) smb[i] = 0;
    __syncthreads();
    if (tid < 128) {
        smb[OFF_V + 13*VSTR + tid]        = 0x3F80;
        smb[BUFH + OFF_V + 13*VSTR + tid] = 0x3F80;
    }
    uint32_t SMB = smem_u32(smb);

    // Q A-fragment (hi only), 1 M-tile of 16 queries per warp
    int Q0 = qt*128 + w*16;
    uint32_t ah[4];
    {
        int r0 = Q0 + g;
        #pragma unroll
        for (int k = 0; k < 2; k++) {
            int dd0 = 2*t + k*8, dd1 = dd0 + 1;
            float q00 = (dd0 < 13) ? Qp[(size_t)dd0*NPIX + r0]     : 0.f;
            float q01 = (dd1 < 13) ? Qp[(size_t)dd1*NPIX + r0]     : 0.f;
            float q10 = (dd0 < 13) ? Qp[(size_t)dd0*NPIX + r0 + 8] : 0.f;
            float q11 = (dd1 < 13) ? Qp[(size_t)dd1*NPIX + r0 + 8] : 0.f;
            ah[2*k]   = (uint32_t)bf16of(q00) | ((uint32_t)bf16of(q01) << 16);
            ah[2*k+1] = (uint32_t)bf16of(q10) | ((uint32_t)bf16of(q11) << 16);
        }
    }

    for (int att = 0; att < 2; att++) {
        const float* Kp = (att ? g_km : g_kh) + (size_t)b*D*NPIX;
        const float* Vp = (att ? g_vm : g_vh) + (size_t)b*D*NPIX;

        float z[2][4];
        #pragma unroll
        for (int nt = 0; nt < 2; nt++)
            #pragma unroll
            for (int i = 0; i < 4; i++) z[nt][i] = 0.f;

        // prefetch tile 0
        float kreg[7], vreg[7];
        #pragma unroll
        for (int j = 0; j < 7; j++) {
            int i = tid + 256*j;
            if (i < 1664) {
                int dd = i >> 7, key = i & 127;
                kreg[j] = Kp[(size_t)dd*NPIX + key];
                vreg[j] = Vp[(size_t)dd*NPIX + key];
            }
        }
        __syncthreads();   // previous att's reads of smb complete
        {
            unsigned short* bK = smb;
            unsigned short* bV = smb + OFF_V;
            #pragma unroll
            for (int j = 0; j < 7; j++) {
                int i = tid + 256*j;
                if (i < 1664) {
                    int dd = i >> 7, key = i & 127;
                    unsigned short h, l;
                    bfsplit(kreg[j], h, l);
                    bK[key*KSTR + dd]           = h;
                    bK[OFF_KLO + key*KSTR + dd] = l;
                    bV[dd*VSTR + key] = bf16of(vreg[j]);
                }
            }
        }
        __syncthreads();

        for (int kt = 0; kt < NKT; kt++) {
            if (kt + 1 < NKT) {
                #pragma unroll
                for (int j = 0; j < 7; j++) {
                    int i = tid + 256*j;
                    if (i < 1664) {
                        int dd = i >> 7, key = i & 127;
                        kreg[j] = Kp[(size_t)dd*NPIX + (kt+1)*128 + key];
                        vreg[j] = Vp[(size_t)dd*NPIX + (kt+1)*128 + key];
                    }
                }
            }

            uint32_t base = SMB + (uint32_t)(kt & 1)*BUFH*2;
            uint32_t KHI = base;
            uint32_t KLO = base + OFF_KLO*2;
            uint32_t VB  = base + OFF_V*2;

            #pragma unroll
            for (int q4 = 0; q4 < 4; q4++) {
                uint32_t bh[8], bl[8];
                int nt_a = q4*4 + (grp >> 1);
                int nt_b = nt_a + 2;
                uint32_t offa = (uint32_t)((nt_a*8 + rr)*48 + (grp & 1)*16);
                uint32_t offb = (uint32_t)((nt_b*8 + rr)*48 + (grp & 1)*16);
                LDM_X4(bh,     KHI + offa);
                LDM_X4(bh + 4, KHI + offb);
                LDM_X4(bl,     KLO + offa);
                LDM_X4(bl + 4, KLO + offb);

                float s[4][4];
                #pragma unroll
                for (int nt = 0; nt < 4; nt++) {
                    #pragma unroll
                    for (int i = 0; i < 4; i++) s[nt][i] = 0.f;
                    MMA_BF16(s[nt], ah, &bh[nt*2]);
                    MMA_BF16(s[nt], ah, &bl[nt*2]);
                }

                uint32_t pa[8];
                #pragma unroll
                for (int j = 0; j < 2; j++) {
                    pa[j*4+0] = bf16pair(ex2f(s[2*j][0]),   ex2f(s[2*j][1]));
                    pa[j*4+1] = bf16pair(ex2f(s[2*j][2]),   ex2f(s[2*j][3]));
                    pa[j*4+2] = bf16pair(ex2f(s[2*j+1][0]), ex2f(s[2*j+1][1]));
                    pa[j*4+3] = bf16pair(ex2f(s[2*j+1][2]), ex2f(s[2*j+1][3]));
                }

                #pragma unroll
                for (int nt2 = 0; nt2 < 2; nt2++) {
                    uint32_t vb[4];
                    uint32_t av = VB + (uint32_t)((nt2*8 + rr)*(VSTR*2)
                                + (16*(q4*2 + (grp >> 1)) + 8*(grp & 1))*2);
                    LDM_X4(vb, av);
                    MMA_BF16(z[nt2], pa,     vb);
                    MMA_BF16(z[nt2], pa + 4, vb + 2);
                }
            }

            if (kt + 1 < NKT) {
                unsigned short* bK = smb + ((kt + 1) & 1)*BUFH;
                unsigned short* bV = bK + OFF_V;
                #pragma unroll
                for (int j = 0; j < 7; j++) {
                    int i = tid + 256*j;
                    if (i < 1664) {
                        int dd = i >> 7, key = i & 127;
                        unsigned short h, l;
                        bfsplit(kreg[j], h, l);
                        bK[key*KSTR + dd]           = h;
                        bK[OFF_KLO + key*KSTR + dd] = l;
                        bV[dd*VSTR + key] = bf16of(vreg[j]);
                    }
                }
                __syncthreads();
            }
        }

        // scatter fragments into plane-layout zbuf[att][col][rowlocal]
        float* zb = zbuf + att*14*128;
        int rl = w*16 + g;
        #pragma unroll
        for (int nt = 0; nt < 2; nt++) {
            int c0 = nt*8 + 2*t, c1 = c0 + 1;
            if (c0 < 14) { zb[c0*128 + rl] = z[nt][0]; zb[c0*128 + rl + 8] = z[nt][2]; }
            if (c1 < 14) { zb[c1*128 + rl] = z[nt][1]; zb[c1*128 + rl + 8] = z[nt][3]; }
        }
    }
    __syncthreads();

    // ---- fused SAM post for this block's 128 pixels ----
    if (tid < 128) {
        int n = qt*128 + tid;
        const float* zh_p = zbuf;
        const float* zm_p = zbuf + 14*128;
        float invH = 1.f/zh_p[13*128 + tid];
        float invM = 1.f/zm_p[13*128 + tid];

        float zh[D], zm[D], hf[D], mf[D];
        #pragma unroll
        for (int d = 0; d < D; d++) {
            zh[d] = zh_p[d*128 + tid]*invH;
            zm[d] = zm_p[d*128 + tid]*invM;
            size_t idx = ((size_t)b*D + d)*NPIX + n;
            hf[d] = g_htmp[idx]; mf[d] = g_m[idx];
        }
        float Z[D];
        #pragma unroll
        for (int o = 0; o < D; o++) {
            float a = 0.f;
            #pragma unroll
            for (int c = 0; c < D; c++) {
                a = fmaf(swz[o*26 + c],      zh[c], a);
                a = fmaf(swz[o*26 + 13 + c], zm[c], a);
            }
            Z[o] = a;
        }
        #pragma unroll
        for (int o = 0; o < D; o++) {
            float ao = 0.f, ag = 0.f, ai = 0.f;
            #pragma unroll
            for (int c = 0; c < D; c++) {
                ao = fmaf(swm[(     o)*26 + c], Z[c], ao); ao = fmaf(swm[(     o)*26 + 13 + c], hf[c], ao);
                ag = fmaf(swm[(13 + o)*26 + c], Z[c], ag); ag = fmaf(swm[(13 + o)*26 + 13 + c], hf[c], ag);
                ai = fmaf(swm[(26 + o)*26 + c], Z[c], ai); ai = fmaf(swm[(26 + o)*26 + 13 + c], hf[c], ai);
            }
            float mi = 1.f/(1.f + __expf(-ai));
            float mn = (1.f - mi)*mf[o] + mi*tanhf(ag);
            size_t idx = ((size_t)b*D + o)*NPIX + n;
            g_m[idx] = mn;
            g_h[idx] = mn/(1.f + __expf(-ao));
        }
    }
}

// ---------------- final 1x1 conv + log_softmax ----------------
__global__ void __launch_bounds__(256) final_logsoftmax(
        const float* __restrict__ Wf, const float* __restrict__ bf,
        float* __restrict__ out) {
    __shared__ float sw[NCL*D], sb2[NCL];
    for (int i = threadIdx.x; i < NCL*D; i += 256) sw[i] = Wf[i];
    if (threadIdx.x < NCL) sb2[threadIdx.x] = bf[threadIdx.x];
    __syncthreads();
    int g = blockIdx.x*256 + threadIdx.x;
    int b = g >> 10, n = g & 1023;
    float cv[D];
    #pragma unroll
    for (int d = 0; d < D; d++) cv[d] = g_c[((size_t)b*D + d)*NPIX + n];
    float l[NCL]; float mx = -INFINITY;
    #pragma unroll
    for (int o = 0; o < NCL; o++) {
        float a = sb2[o];
        #pragma unroll
        for (int d = 0; d < D; d++) a = fmaf(sw[o*13 + d], cv[d], a);
        l[o] = a; mx = fmaxf(mx, a);
    }
    float sum = 0.f;
    #pragma unroll
    for (int o = 0; o < NCL; o++) sum += __expf(l[o] - mx);
    float lse = mx + logf(sum);
    #pragma unroll
    for (int o = 0; o < NCL; o++)
        out[((size_t)b*NCL + o)*NPIX + n] = l[o] - lse;
}

// ---------------- launch ----------------
extern "C" void kernel_launch(void* const* d_in, const int* in_sizes, int n_in,
                              void* d_out, int out_size) {
    const float* x1  = (const float*)d_in[0];
    const float* Wg  = (const float*)d_in[1];
    const float* Wq  = (const float*)d_in[2];
    const float* Wkh = (const float*)d_in[3];
    const float* Wvh = (const float*)d_in[4];
    const float* Wkm = (const float*)d_in[5];
    const float* Wvm = (const float*)d_in[6];
    const float* Wz  = (const float*)d_in[7];
    const float* Wm  = (const float*)d_in[8];
    const float* Wf  = (const float*)d_in[9];
    const float* bf  = (const float*)d_in[10];
    float* out = (float*)d_out;

    cudaFuncSetAttribute(conv_lstm_proj, cudaFuncAttributeMaxDynamicSharedMemorySize, CONV_SMEM5);
    cudaFuncSetAttribute(sam_attn_post, cudaFuncAttributeMaxDynamicSharedMemorySize, ATTN_SMEM);

    zero_state<<<256, 256>>>();
    pack_conv_weights<<<(CONV_WP + 255)/256, 256>>>(Wg);
    for (int t = 0; t < TSTEPS; t++) {
        conv_lstm_proj<<<dim3(8, BATCH), 256, CONV_SMEM5>>>(x1, t, Wq, Wkh, Wvh, Wkm, Wvm);
        sam_attn_post<<<dim3(8, BATCH), 256, ATTN_SMEM>>>(Wz, Wm);
    }
    final_logsoftmax<<<128, 256>>>(Wf, bf, out);
}

// round 15
// speedup vs baseline: 1.0556x; 1.0556x over previous
#include <cuda_runtime.h>
#include <cuda_bf16.h>
#include <math.h>
#include <cstdint>

#define D      13
#define NPIX   1024
#define BATCH  32
#define TSTEPS 24
#define NCL    8
#define NKT    8        // key tiles of 128

typedef unsigned long long u64;

// ---------------- f32x2 helpers (conv path) ----------------
__device__ __forceinline__ u64 fma2(u64 a, u64 b, u64 c) {
    u64 d; asm("fma.rn.f32x2 %0, %1, %2, %3;" : "=l"(d) : "l"(a), "l"(b), "l"(c)); return d;
}
__device__ __forceinline__ u64 pack2(float lo, float hi) {
    u64 d; asm("mov.b64 %0, {%1, %2};" : "=l"(d) : "f"(lo), "f"(hi)); return d;
}
__device__ __forceinline__ void unpack2(u64 v, float& lo, float& hi) {
    asm("mov.b64 {%0, %1}, %2;" : "=f"(lo), "=f"(hi) : "l"(v));
}
__device__ __forceinline__ float ex2f(float x) {
    float r; asm("ex2.approx.f32 %0, %1;" : "=f"(r) : "f"(x)); return r;
}

// ---------------- MMA helpers (sm_80+ PTX, no arch-gated features) ----------------
__device__ __forceinline__ uint32_t smem_u32(const void* p) {
    uint32_t a; asm("{ .reg .u64 t; cvta.to.shared.u64 t, %1; cvt.u32.u64 %0, t; }" : "=r"(a) : "l"(p));
    return a;
}
__device__ __forceinline__ void bfsplit(float x, unsigned short& h, unsigned short& l) {
    asm("cvt.rn.bf16.f32 %0, %1;" : "=h"(h) : "f"(x));
    float hf = __uint_as_float(((unsigned)h) << 16);
    float r = x - hf;
    asm("cvt.rn.bf16.f32 %0, %1;" : "=h"(l) : "f"(r));
}
__device__ __forceinline__ unsigned short bf16of(float x) {
    unsigned short h; asm("cvt.rn.bf16.f32 %0, %1;" : "=h"(h) : "f"(x)); return h;
}
__device__ __forceinline__ uint32_t bf16pair(float lo, float hi) {
    uint32_t r; asm("cvt.rn.bf16x2.f32 %0, %1, %2;" : "=r"(r) : "f"(hi), "f"(lo)); return r;
}
#define MMA_BF16(dd, a, b) \
    asm volatile("mma.sync.aligned.m16n8k16.row.col.f32.bf16.bf16.f32 " \
        "{%0,%1,%2,%3}, {%4,%5,%6,%7}, {%8,%9}, {%0,%1,%2,%3};" \
        : "+f"((dd)[0]),"+f"((dd)[1]),"+f"((dd)[2]),"+f"((dd)[3]) \
        : "r"((a)[0]),"r"((a)[1]),"r"((a)[2]),"r"((a)[3]), "r"((b)[0]),"r"((b)[1]))
#define LDM_X4(r, addr) \
    asm volatile("ldmatrix.sync.aligned.m8n8.x4.shared.b16 {%0,%1,%2,%3}, [%4];" \
        : "=r"((r)[0]),"=r"((r)[1]),"=r"((r)[2]),"=r"((r)[3]) : "r"(addr))

// ---------------- persistent state ----------------
__device__ float g_c   [BATCH*D*NPIX];
__device__ float g_h   [BATCH*D*NPIX];
__device__ float g_m   [BATCH*D*NPIX];
__device__ float g_htmp[BATCH*D*NPIX];
__device__ float g_q   [BATCH*D*NPIX];   // pre-scaled by log2(e)
__device__ float g_kh  [BATCH*D*NPIX];
__device__ float g_vh  [BATCH*D*NPIX];
__device__ float g_km  [BATCH*D*NPIX];
__device__ float g_vm  [BATCH*D*NPIX];
__device__ float g_part[2*BATCH*14*NPIX]; // [att][b][d|sum][n]

__global__ void zero_state() {
    int total = BATCH*D*NPIX;
    for (int i = blockIdx.x*blockDim.x + threadIdx.x; i < total; i += gridDim.x*blockDim.x) {
        g_c[i] = 0.f; g_h[i] = 0.f; g_m[i] = 0.f;
    }
}

// ---------------- conv weight pre-pack ----------------
#define CONV_WP (13*26*9)
__device__ u64 g_wif[CONV_WP];
__device__ u64 g_wgo[CONV_WP];

__global__ void pack_conv_weights(const float* __restrict__ Wg) {
    int i = blockIdx.x*256 + threadIdx.x;
    if (i < CONV_WP) {
        int d = i / 234, r = i % 234;
        g_wif[i] = pack2(Wg[(     d)*234 + r], Wg[(13 + d)*234 + r]);
        g_wgo[i] = pack2(Wg[(26 + d)*234 + r], Wg[(39 + d)*234 + r]);
    }
}

// ---------------- ConvLSTM step + fused SAM projections: 2 pixels/thread, 2 d-groups ----------------
#define CONV_TILE_F3 (26*10*34)     // 8840 floats (8-row tile + halo)
#define PROJ_W_F     (5*169)
#define CONV_SMEM6   (2*CONV_WP*8 + CONV_TILE_F3*4 + PROJ_W_F*4 + 13*256*4)

__global__ void __launch_bounds__(256) conv_lstm_proj(
        const float* __restrict__ x1, int t,
        const float* __restrict__ Wq,  const float* __restrict__ Wkh,
        const float* __restrict__ Wvh, const float* __restrict__ Wkm,
        const float* __restrict__ Wvm) {
    extern __shared__ char smraw[];
    u64*   swif = (u64*)smraw;
    u64*   swgo = swif + CONV_WP;
    float* st   = (float*)(swgo + CONV_WP);   // [26][10][34]
    float* spw  = st + CONV_TILE_F3;          // 845
    float* sht  = spw + PROJ_W_F;             // [13][256]

    int b  = blockIdx.y;
    int y0 = blockIdx.x * 8;

    const ulonglong2* gi = (const ulonglong2*)g_wif;
    const ulonglong2* go = (const ulonglong2*)g_wgo;
    ulonglong2* si = (ulonglong2*)swif;
    ulonglong2* so = (ulonglong2*)swgo;
    for (int i = threadIdx.x; i < CONV_WP/2; i += 256) { si[i] = gi[i]; so[i] = go[i]; }
    if (threadIdx.x == 0) { swif[CONV_WP-1] = g_wif[CONV_WP-1]; swgo[CONV_WP-1] = g_wgo[CONV_WP-1]; }
    for (int i = threadIdx.x; i < PROJ_W_F; i += 256) {
        spw[i] = (i < 169) ? Wq[i] : (i < 338) ? Wkh[i-169] : (i < 507) ? Wvh[i-338]
               : (i < 676) ? Wkm[i-507] : Wvm[i-676];
    }
    for (int i = threadIdx.x; i < CONV_TILE_F3; i += 256) {
        int ci = i / 340; int rem = i % 340; int rr = rem / 34; int cc = rem % 34;
        int y = y0 + rr - 1, x = cc - 1;
        float v = 0.f;
        if ((unsigned)y < 32u && (unsigned)x < 32u) {
            int n = y*32 + x;
            v = (ci < 13) ? x1[(((size_t)b*TSTEPS + t)*D + ci)*NPIX + n]
                          : g_h[((size_t)b*D + (ci-13))*NPIX + n];
        }
        st[i] = v;
    }
    __syncthreads();

    int px  = threadIdx.x & 127;       // 0..127
    int grp = threadIdx.x >> 7;        // 0: d 0..6 + proj(q,kh); 1: d 7..12 + proj(vh,km,vm)
    int r = px >> 5, c = px & 31;      // r in 0..3; pixels (y0+r, c) and (y0+r+4, c)
    int n0 = (y0 + r)*32 + c;
    int n1 = (y0 + r + 4)*32 + c;
    int d0 = grp * 7;
    int nd = grp ? 6 : 7;

    u64 aif0[7], ago0[7], aif1[7], ago1[7];
    #pragma unroll
    for (int dd = 0; dd < 7; dd++) { aif0[dd] = 0ull; ago0[dd] = 0ull; aif1[dd] = 0ull; ago1[dd] = 0ull; }

    for (int ci = 0; ci < 26; ci++) {
        const float* tb = st + ci*340 + r*34 + c;
        #pragma unroll
        for (int ky = 0; ky < 3; ky++) {
            #pragma unroll
            for (int kx = 0; kx < 3; kx++) {
                float v0 = tb[ky*34 + kx];
                float v1 = tb[(ky + 4)*34 + kx];
                u64 vv0 = pack2(v0, v0);
                u64 vv1 = pack2(v1, v1);
                int rt = ci*9 + ky*3 + kx;
                #pragma unroll
                for (int dd = 0; dd < 7; dd++) {
                    if (dd < nd) {
                        u64 wif = swif[(d0+dd)*234 + rt];
                        u64 wgo = swgo[(d0+dd)*234 + rt];
                        aif0[dd] = fma2(wif, vv0, aif0[dd]);
                        ago0[dd] = fma2(wgo, vv0, ago0[dd]);
                        aif1[dd] = fma2(wif, vv1, aif1[dd]);
                        ago1[dd] = fma2(wgo, vv1, ago1[dd]);
                    }
                }
            }
        }
    }

    #pragma unroll
    for (int dd = 0; dd < 7; dd++) {
        if (dd < nd) {
            int d = d0 + dd;
            // pixel 0
            {
                float ai, af, ag, ao;
                unpack2(aif0[dd], ai, af);
                unpack2(ago0[dd], ag, ao);
                float ig = 1.f/(1.f + __expf(-ai));
                float fg = 1.f/(1.f + __expf(-af));
                float og = 1.f/(1.f + __expf(-ao));
                float gg = tanhf(ag);
                size_t idx = ((size_t)b*D + d)*NPIX + n0;
                float cn = fg*g_c[idx] + ig*gg;
                g_c[idx] = cn;
                float htv = og*tanhf(cn);
                g_htmp[idx] = htv;
                sht[d*256 + px] = htv;
            }
            // pixel 1
            {
                float ai, af, ag, ao;
                unpack2(aif1[dd], ai, af);
                unpack2(ago1[dd], ag, ao);
                float ig = 1.f/(1.f + __expf(-ai));
                float fg = 1.f/(1.f + __expf(-af));
                float og = 1.f/(1.f + __expf(-ao));
                float gg = tanhf(ag);
                size_t idx = ((size_t)b*D + d)*NPIX + n1;
                float cn = fg*g_c[idx] + ig*gg;
                g_c[idx] = cn;
                float htv = og*tanhf(cn);
                g_htmp[idx] = htv;
                sht[d*256 + 128 + px] = htv;
            }
        }
    }
    __syncthreads();

    const float L2E = 1.44269504f;
    #pragma unroll
    for (int p = 0; p < 2; p++) {
        int n = p ? n1 : n0;
        int sx = p*128 + px;
        size_t pb = (size_t)b*D*NPIX + n;
        if (grp == 0) {
            float ht[D];
            #pragma unroll
            for (int d = 0; d < D; d++) ht[d] = sht[d*256 + sx];
            #pragma unroll
            for (int o = 0; o < D; o++) {
                float q = 0.f, kh = 0.f;
                #pragma unroll
                for (int d = 0; d < D; d++) {
                    q  = fmaf(spw[      o*13 + d], ht[d], q);
                    kh = fmaf(spw[169 + o*13 + d], ht[d], kh);
                }
                g_q [pb + (size_t)o*NPIX] = q*L2E;
                g_kh[pb + (size_t)o*NPIX] = kh;
            }
        } else {
            float ht[D], mv[D];
            #pragma unroll
            for (int d = 0; d < D; d++) {
                ht[d] = sht[d*256 + sx];
                mv[d] = g_m[((size_t)b*D + d)*NPIX + n];
            }
            #pragma unroll
            for (int o = 0; o < D; o++) {
                float vh = 0.f, km = 0.f, vm = 0.f;
                #pragma unroll
                for (int d = 0; d < D; d++) {
                    vh = fmaf(spw[338 + o*13 + d], ht[d], vh);
                    km = fmaf(spw[507 + o*13 + d], mv[d], km);
                    vm = fmaf(spw[676 + o*13 + d], mv[d], vm);
                }
                g_vh[pb + (size_t)o*NPIX] = vh;
                g_km[pb + (size_t)o*NPIX] = km;
                g_vm[pb + (size_t)o*NPIX] = vm;
            }
        }
    }
}

// ---------------- warp-MMA flash attention (R13, unchanged) ----------------
#define KSTR 24
#define VSTR 136
#define VROWS 16
#define BUFH (2*128*KSTR + VROWS*VSTR)
#define OFF_KLO (128*KSTR)
#define OFF_V   (2*128*KSTR)

__global__ void __launch_bounds__(256, 2) sam_attn_mma() {
    __shared__ unsigned short smb[2*BUFH];

    int tid = threadIdx.x;
    int w    = tid >> 5;
    int lane = tid & 31;
    int g = lane >> 2, t = lane & 3;
    int grp = lane >> 3, rr = lane & 7;

    int qt  = blockIdx.x;
    int b   = blockIdx.y;
    int att = blockIdx.z;

    const float* Qp = g_q + (size_t)b*D*NPIX;
    const float* Kp = (att ? g_km : g_kh) + (size_t)b*D*NPIX;
    const float* Vp = (att ? g_vm : g_vh) + (size_t)b*D*NPIX;

    for (int i = tid; i < 2*BUFH; i += 256) smb[i] = 0;
    __syncthreads();
    if (tid < 128) {
        smb[OFF_V + 13*VSTR + tid]        = 0x3F80;
        smb[BUFH + OFF_V + 13*VSTR + tid] = 0x3F80;
    }

    uint32_t SMB = smem_u32(smb);

    int Q0 = qt*256 + w*32;
    uint32_t ah[2][4];
    #pragma unroll
    for (int m = 0; m < 2; m++) {
        int r0 = Q0 + m*16 + g;
        #pragma unroll
        for (int k = 0; k < 2; k++) {
            int dd0 = 2*t + k*8, dd1 = dd0 + 1;
            float q00 = (dd0 < 13) ? Qp[(size_t)dd0*NPIX + r0]     : 0.f;
            float q01 = (dd1 < 13) ? Qp[(size_t)dd1*NPIX + r0]     : 0.f;
            float q10 = (dd0 < 13) ? Qp[(size_t)dd0*NPIX + r0 + 8] : 0.f;
            float q11 = (dd1 < 13) ? Qp[(size_t)dd1*NPIX + r0 + 8] : 0.f;
            ah[m][2*k]   = (uint32_t)bf16of(q00) | ((uint32_t)bf16of(q01) << 16);
            ah[m][2*k+1] = (uint32_t)bf16of(q10) | ((uint32_t)bf16of(q11) << 16);
        }
    }

    float z[2][2][4];
    #pragma unroll
    for (int m = 0; m < 2; m++)
        #pragma unroll
        for (int nt = 0; nt < 2; nt++)
            #pragma unroll
            for (int i = 0; i < 4; i++) z[m][nt][i] = 0.f;

    float kreg[7], vreg[7];
    #pragma unroll
    for (int j = 0; j < 7; j++) {
        int i = tid + 256*j;
        if (i < 1664) {
            int dd = i >> 7, key = i & 127;
            kreg[j] = Kp[(size_t)dd*NPIX + key];
            vreg[j] = Vp[(size_t)dd*NPIX + key];
        }
    }
    {
        unsigned short* bK = smb;
        unsigned short* bV = smb + OFF_V;
        #pragma unroll
        for (int j = 0; j < 7; j++) {
            int i = tid + 256*j;
            if (i < 1664) {
                int dd = i >> 7, key = i & 127;
                unsigned short h, l;
                bfsplit(kreg[j], h, l);
                bK[key*KSTR + dd]           = h;
                bK[OFF_KLO + key*KSTR + dd] = l;
                bV[dd*VSTR + key] = bf16of(vreg[j]);
            }
        }
    }
    __syncthreads();

    for (int kt = 0; kt < NKT; kt++) {
        if (kt + 1 < NKT) {
            #pragma unroll
            for (int j = 0; j < 7; j++) {
                int i = tid + 256*j;
                if (i < 1664) {
                    int dd = i >> 7, key = i & 127;
                    kreg[j] = Kp[(size_t)dd*NPIX + (kt+1)*128 + key];
                    vreg[j] = Vp[(size_t)dd*NPIX + (kt+1)*128 + key];
                }
            }
        }

        uint32_t base = SMB + (uint32_t)(kt & 1)*BUFH*2;
        uint32_t KHI = base;
        uint32_t KLO = base + OFF_KLO*2;
        uint32_t VB  = base + OFF_V*2;

        #pragma unroll
        for (int m = 0; m < 2; m++) {
            #pragma unroll
            for (int q4 = 0; q4 < 4; q4++) {
                uint32_t bh[8], bl[8];
                int nt_a = q4*4 + (grp >> 1);
                int nt_b = nt_a + 2;
                uint32_t offa = (uint32_t)((nt_a*8 + rr)*48 + (grp & 1)*16);
                uint32_t offb = (uint32_t)((nt_b*8 + rr)*48 + (grp & 1)*16);
                LDM_X4(bh,     KHI + offa);
                LDM_X4(bh + 4, KHI + offb);
                LDM_X4(bl,     KLO + offa);
                LDM_X4(bl + 4, KLO + offb);

                float s[4][4];
                #pragma unroll
                for (int nt = 0; nt < 4; nt++) {
                    #pragma unroll
                    for (int i = 0; i < 4; i++) s[nt][i] = 0.f;
                    MMA_BF16(s[nt], ah[m], &bh[nt*2]);
                    MMA_BF16(s[nt], ah[m], &bl[nt*2]);
                }

                uint32_t pa[8];
                #pragma unroll
                for (int j = 0; j < 2; j++) {
                    pa[j*4+0] = bf16pair(ex2f(s[2*j][0]),   ex2f(s[2*j][1]));
                    pa[j*4+1] = bf16pair(ex2f(s[2*j][2]),   ex2f(s[2*j][3]));
                    pa[j*4+2] = bf16pair(ex2f(s[2*j+1][0]), ex2f(s[2*j+1][1]));
                    pa[j*4+3] = bf16pair(ex2f(s[2*j+1][2]), ex2f(s[2*j+1][3]));
                }

                #pragma unroll
                for (int nt2 = 0; nt2 < 2; nt2++) {
                    uint32_t vb[4];
                    uint32_t av = VB + (uint32_t)((nt2*8 + rr)*(VSTR*2)
                                + (16*(q4*2 + (grp >> 1)) + 8*(grp & 1))*2);
                    LDM_X4(vb, av);
                    MMA_BF16(z[m][nt2], pa,     vb);
                    MMA_BF16(z[m][nt2], pa + 4, vb + 2);
                }
            }
        }

        if (kt + 1 < NKT) {
            unsigned short* bK = smb + ((kt + 1) & 1)*BUFH;
            unsigned short* bV = bK + OFF_V;
            #pragma unroll
            for (int j = 0; j < 7; j++) {
                int i = tid + 256*j;
                if (i < 1664) {
                    int dd = i >> 7, key = i & 127;
                    unsigned short h, l;
                    bfsplit(kreg[j], h, l);
                    bK[key*KSTR + dd]           = h;
                    bK[OFF_KLO + key*KSTR + dd] = l;
                    bV[dd*VSTR + key] = bf16of(vreg[j]);
                }
            }
            __syncthreads();
        }
    }

    float* ob = g_part + (size_t)(att*BATCH + b)*14*NPIX;
    #pragma unroll
    for (int m = 0; m < 2; m++) {
        int r0 = Q0 + m*16 + g;
        #pragma unroll
        for (int nt = 0; nt < 2; nt++) {
            int dd0 = nt*8 + 2*t, dd1 = dd0 + 1;
            if (dd0 < 14) {
                ob[(size_t)dd0*NPIX + r0]     = z[m][nt][0];
                ob[(size_t)dd0*NPIX + r0 + 8] = z[m][nt][2];
            }
            if (dd1 < 14) {
                ob[(size_t)dd1*NPIX + r0]     = z[m][nt][1];
                ob[(size_t)dd1*NPIX + r0 + 8] = z[m][nt][3];
            }
        }
    }
}

// ---------------- SAM fuse + state update (R13, unchanged) ----------------
__global__ void __launch_bounds__(256) sam_post(
        const float* __restrict__ Wz, const float* __restrict__ Wm) {
    __shared__ float swz[13*26], swm[39*26];
    for (int i = threadIdx.x; i < 13*26; i += 256) swz[i] = Wz[i];
    for (int i = threadIdx.x; i < 39*26; i += 256) swm[i] = Wm[i];
    __syncthreads();
    int g = blockIdx.x*256 + threadIdx.x;
    int b = g >> 10, n = g & 1023;

    const float* ph = g_part + ((size_t)b*14)*NPIX + n;
    const float* pm = g_part + ((size_t)(BATCH + b)*14)*NPIX + n;
    float invH = 1.f/ph[(size_t)13*NPIX];
    float invM = 1.f/pm[(size_t)13*NPIX];

    float zh[D], zm[D], hf[D], mf[D];
    #pragma unroll
    for (int d = 0; d < D; d++) {
        zh[d] = ph[(size_t)d*NPIX]*invH;
        zm[d] = pm[(size_t)d*NPIX]*invM;
        size_t idx = ((size_t)b*D + d)*NPIX + n;
        hf[d] = g_htmp[idx]; mf[d] = g_m[idx];
    }
    float Z[D];
    #pragma unroll
    for (int o = 0; o < D; o++) {
        float a = 0.f;
        #pragma unroll
        for (int c = 0; c < D; c++) {
            a = fmaf(swz[o*26 + c],      zh[c], a);
            a = fmaf(swz[o*26 + 13 + c], zm[c], a);
        }
        Z[o] = a;
    }
    #pragma unroll
    for (int o = 0; o < D; o++) {
        float ao = 0.f, ag = 0.f, ai = 0.f;
        #pragma unroll
        for (int c = 0; c < D; c++) {
            ao = fmaf(swm[(     o)*26 + c], Z[c], ao); ao = fmaf(swm[(     o)*26 + 13 + c], hf[c], ao);
            ag = fmaf(swm[(13 + o)*26 + c], Z[c], ag); ag = fmaf(swm[(13 + o)*26 + 13 + c], hf[c], ag);
            ai = fmaf(swm[(26 + o)*26 + c], Z[c], ai); ai = fmaf(swm[(26 + o)*26 + 13 + c], hf[c], ai);
        }
        float mi = 1.f/(1.f + __expf(-ai));
        float mn = (1.f - mi)*mf[o] + mi*tanhf(ag);
        size_t idx = ((size_t)b*D + o)*NPIX + n;
        g_m[idx] = mn;
        g_h[idx] = mn/(1.f + __expf(-ao));
    }
}

// ---------------- final 1x1 conv + log_softmax ----------------
__global__ void __launch_bounds__(256) final_logsoftmax(
        const float* __restrict__ Wf, const float* __restrict__ bf,
        float* __restrict__ out) {
    __shared__ float sw[NCL*D], sb2[NCL];
    for (int i = threadIdx.x; i < NCL*D; i += 256) sw[i] = Wf[i];
    if (threadIdx.x < NCL) sb2[threadIdx.x] = bf[threadIdx.x];
    __syncthreads();
    int g = blockIdx.x*256 + threadIdx.x;
    int b = g >> 10, n = g & 1023;
    float cv[D];
    #pragma unroll
    for (int d = 0; d < D; d++) cv[d] = g_c[((size_t)b*D + d)*NPIX + n];
    float l[NCL]; float mx = -INFINITY;
    #pragma unroll
    for (int o = 0; o < NCL; o++) {
        float a = sb2[o];
        #pragma unroll
        for (int d = 0; d < D; d++) a = fmaf(sw[o*13 + d], cv[d], a);
        l[o] = a; mx = fmaxf(mx, a);
    }
    float sum = 0.f;
    #pragma unroll
    for (int o = 0; o < NCL; o++) sum += __expf(l[o] - mx);
    float lse = mx + logf(sum);
    #pragma unroll
    for (int o = 0; o < NCL; o++)
        out[((size_t)b*NCL + o)*NPIX + n] = l[o] - lse;
}

// ---------------- launch ----------------
extern "C" void kernel_launch(void* const* d_in, const int* in_sizes, int n_in,
                              void* d_out, int out_size) {
    const float* x1  = (const float*)d_in[0];
    const float* Wg  = (const float*)d_in[1];
    const float* Wq  = (const float*)d_in[2];
    const float* Wkh = (const float*)d_in[3];
    const float* Wvh = (const float*)d_in[4];
    const float* Wkm = (const float*)d_in[5];
    const float* Wvm = (const float*)d_in[6];
    const float* Wz  = (const float*)d_in[7];
    const float* Wm  = (const float*)d_in[8];
    const float* Wf  = (const float*)d_in[9];
    const float* bf  = (const float*)d_in[10];
    float* out = (float*)d_out;

    cudaFuncSetAttribute(conv_lstm_proj, cudaFuncAttributeMaxDynamicSharedMemorySize, CONV_SMEM6);

    zero_state<<<256, 256>>>();
    pack_conv_weights<<<(CONV_WP + 255)/256, 256>>>(Wg);
    for (int t = 0; t < TSTEPS; t++) {
        conv_lstm_proj<<<dim3(4, BATCH), 256, CONV_SMEM6>>>(x1, t, Wq, Wkh, Wvh, Wkm, Wvm);
        sam_attn_mma<<<dim3(4, BATCH, 2), 256>>>();
        sam_post<<<128, 256>>>(Wz, Wm);
    }
    final_logsoftmax<<<128, 256>>>(Wf, bf, out);
}

// round 16
// speedup vs baseline: 1.0785x; 1.0217x over previous
#include <cuda_runtime.h>
#include <cuda_bf16.h>
#include <math.h>
#include <cstdint>

#define D      13
#define NPIX   1024
#define BATCH  32
#define TSTEPS 24
#define NCL    8
#define NKT    8        // key tiles of 128

typedef unsigned long long u64;

// ---------------- f32x2 helpers (conv path) ----------------
__device__ __forceinline__ u64 fma2(u64 a, u64 b, u64 c) {
    u64 d; asm("fma.rn.f32x2 %0, %1, %2, %3;" : "=l"(d) : "l"(a), "l"(b), "l"(c)); return d;
}
__device__ __forceinline__ u64 pack2(float lo, float hi) {
    u64 d; asm("mov.b64 %0, {%1, %2};" : "=l"(d) : "f"(lo), "f"(hi)); return d;
}
__device__ __forceinline__ void unpack2(u64 v, float& lo, float& hi) {
    asm("mov.b64 {%0, %1}, %2;" : "=f"(lo), "=f"(hi) : "l"(v));
}
__device__ __forceinline__ float ex2f(float x) {
    float r; asm("ex2.approx.f32 %0, %1;" : "=f"(r) : "f"(x)); return r;
}

// ---------------- MMA helpers ----------------
__device__ __forceinline__ uint32_t smem_u32(const void* p) {
    uint32_t a; asm("{ .reg .u64 t; cvta.to.shared.u64 t, %1; cvt.u32.u64 %0, t; }" : "=r"(a) : "l"(p));
    return a;
}
__device__ __forceinline__ void bfsplit(float x, unsigned short& h, unsigned short& l) {
    asm("cvt.rn.bf16.f32 %0, %1;" : "=h"(h) : "f"(x));
    float hf = __uint_as_float(((unsigned)h) << 16);
    float r = x - hf;
    asm("cvt.rn.bf16.f32 %0, %1;" : "=h"(l) : "f"(r));
}
__device__ __forceinline__ unsigned short bf16of(float x) {
    unsigned short h; asm("cvt.rn.bf16.f32 %0, %1;" : "=h"(h) : "f"(x)); return h;
}
__device__ __forceinline__ uint32_t bf16pair(float lo, float hi) {
    uint32_t r; asm("cvt.rn.bf16x2.f32 %0, %1, %2;" : "=r"(r) : "f"(hi), "f"(lo)); return r;
}
#define MMA_BF16(dd, a, b) \
    asm volatile("mma.sync.aligned.m16n8k16.row.col.f32.bf16.bf16.f32 " \
        "{%0,%1,%2,%3}, {%4,%5,%6,%7}, {%8,%9}, {%0,%1,%2,%3};" \
        : "+f"((dd)[0]),"+f"((dd)[1]),"+f"((dd)[2]),"+f"((dd)[3]) \
        : "r"((a)[0]),"r"((a)[1]),"r"((a)[2]),"r"((a)[3]), "r"((b)[0]),"r"((b)[1]))
#define LDM_X4(r, addr) \
    asm volatile("ldmatrix.sync.aligned.m8n8.x4.shared.b16 {%0,%1,%2,%3}, [%4];" \
        : "=r"((r)[0]),"=r"((r)[1]),"=r"((r)[2]),"=r"((r)[3]) : "r"(addr))

// ---------------- persistent state ----------------
__device__ float g_c   [BATCH*D*NPIX];
__device__ float g_h   [BATCH*D*NPIX];
__device__ float g_m   [BATCH*D*NPIX];
__device__ float g_htmp[BATCH*D*NPIX];
__device__ float g_q   [BATCH*D*NPIX];   // pre-scaled by log2(e)
__device__ float g_kh  [BATCH*D*NPIX];
__device__ float g_vh  [BATCH*D*NPIX];
__device__ float g_km  [BATCH*D*NPIX];
__device__ float g_vm  [BATCH*D*NPIX];
__device__ float g_part[2*BATCH*14*NPIX]; // [att][b][d|sum][n]

__global__ void zero_state() {
    int total = BATCH*D*NPIX;
    for (int i = blockIdx.x*blockDim.x + threadIdx.x; i < total; i += gridDim.x*blockDim.x) {
        g_c[i] = 0.f; g_h[i] = 0.f; g_m[i] = 0.f;
    }
}

// ---------------- conv weight pre-pack ----------------
#define CONV_WP (13*26*9)
__device__ u64 g_wif[CONV_WP];
__device__ u64 g_wgo[CONV_WP];

__global__ void pack_conv_weights(const float* __restrict__ Wg) {
    int i = blockIdx.x*256 + threadIdx.x;
    if (i < CONV_WP) {
        int d = i / 234, r = i % 234;
        g_wif[i] = pack2(Wg[(     d)*234 + r], Wg[(13 + d)*234 + r]);
        g_wgo[i] = pack2(Wg[(26 + d)*234 + r], Wg[(39 + d)*234 + r]);
    }
}

// ---------------- ConvLSTM step + fused SAM projections (R15, unchanged) ----------------
#define CONV_TILE_F3 (26*10*34)
#define PROJ_W_F     (5*169)
#define CONV_SMEM6   (2*CONV_WP*8 + CONV_TILE_F3*4 + PROJ_W_F*4 + 13*256*4)

__global__ void __launch_bounds__(256) conv_lstm_proj(
        const float* __restrict__ x1, int t,
        const float* __restrict__ Wq,  const float* __restrict__ Wkh,
        const float* __restrict__ Wvh, const float* __restrict__ Wkm,
        const float* __restrict__ Wvm) {
    extern __shared__ char smraw[];
    u64*   swif = (u64*)smraw;
    u64*   swgo = swif + CONV_WP;
    float* st   = (float*)(swgo + CONV_WP);
    float* spw  = st + CONV_TILE_F3;
    float* sht  = spw + PROJ_W_F;

    int b  = blockIdx.y;
    int y0 = blockIdx.x * 8;

    const ulonglong2* gi = (const ulonglong2*)g_wif;
    const ulonglong2* go = (const ulonglong2*)g_wgo;
    ulonglong2* si = (ulonglong2*)swif;
    ulonglong2* so = (ulonglong2*)swgo;
    for (int i = threadIdx.x; i < CONV_WP/2; i += 256) { si[i] = gi[i]; so[i] = go[i]; }
    if (threadIdx.x == 0) { swif[CONV_WP-1] = g_wif[CONV_WP-1]; swgo[CONV_WP-1] = g_wgo[CONV_WP-1]; }
    for (int i = threadIdx.x; i < PROJ_W_F; i += 256) {
        spw[i] = (i < 169) ? Wq[i] : (i < 338) ? Wkh[i-169] : (i < 507) ? Wvh[i-338]
               : (i < 676) ? Wkm[i-507] : Wvm[i-676];
    }
    for (int i = threadIdx.x; i < CONV_TILE_F3; i += 256) {
        int ci = i / 340; int rem = i % 340; int rr = rem / 34; int cc = rem % 34;
        int y = y0 + rr - 1, x = cc - 1;
        float v = 0.f;
        if ((unsigned)y < 32u && (unsigned)x < 32u) {
            int n = y*32 + x;
            v = (ci < 13) ? x1[(((size_t)b*TSTEPS + t)*D + ci)*NPIX + n]
                          : g_h[((size_t)b*D + (ci-13))*NPIX + n];
        }
        st[i] = v;
    }
    __syncthreads();

    int px  = threadIdx.x & 127;
    int grp = threadIdx.x >> 7;
    int r = px >> 5, c = px & 31;
    int n0 = (y0 + r)*32 + c;
    int n1 = (y0 + r + 4)*32 + c;
    int d0 = grp * 7;
    int nd = grp ? 6 : 7;

    u64 aif0[7], ago0[7], aif1[7], ago1[7];
    #pragma unroll
    for (int dd = 0; dd < 7; dd++) { aif0[dd] = 0ull; ago0[dd] = 0ull; aif1[dd] = 0ull; ago1[dd] = 0ull; }

    for (int ci = 0; ci < 26; ci++) {
        const float* tb = st + ci*340 + r*34 + c;
        #pragma unroll
        for (int ky = 0; ky < 3; ky++) {
            #pragma unroll
            for (int kx = 0; kx < 3; kx++) {
                float v0 = tb[ky*34 + kx];
                float v1 = tb[(ky + 4)*34 + kx];
                u64 vv0 = pack2(v0, v0);
                u64 vv1 = pack2(v1, v1);
                int rt = ci*9 + ky*3 + kx;
                #pragma unroll
                for (int dd = 0; dd < 7; dd++) {
                    if (dd < nd) {
                        u64 wif = swif[(d0+dd)*234 + rt];
                        u64 wgo = swgo[(d0+dd)*234 + rt];
                        aif0[dd] = fma2(wif, vv0, aif0[dd]);
                        ago0[dd] = fma2(wgo, vv0, ago0[dd]);
                        aif1[dd] = fma2(wif, vv1, aif1[dd]);
                        ago1[dd] = fma2(wgo, vv1, ago1[dd]);
                    }
                }
            }
        }
    }

    #pragma unroll
    for (int dd = 0; dd < 7; dd++) {
        if (dd < nd) {
            int d = d0 + dd;
            {
                float ai, af, ag, ao;
                unpack2(aif0[dd], ai, af);
                unpack2(ago0[dd], ag, ao);
                float ig = 1.f/(1.f + __expf(-ai));
                float fg = 1.f/(1.f + __expf(-af));
                float og = 1.f/(1.f + __expf(-ao));
                float gg = tanhf(ag);
                size_t idx = ((size_t)b*D + d)*NPIX + n0;
                float cn = fg*g_c[idx] + ig*gg;
                g_c[idx] = cn;
                float htv = og*tanhf(cn);
                g_htmp[idx] = htv;
                sht[d*256 + px] = htv;
            }
            {
                float ai, af, ag, ao;
                unpack2(aif1[dd], ai, af);
                unpack2(ago1[dd], ag, ao);
                float ig = 1.f/(1.f + __expf(-ai));
                float fg = 1.f/(1.f + __expf(-af));
                float og = 1.f/(1.f + __expf(-ao));
                float gg = tanhf(ag);
                size_t idx = ((size_t)b*D + d)*NPIX + n1;
                float cn = fg*g_c[idx] + ig*gg;
                g_c[idx] = cn;
                float htv = og*tanhf(cn);
                g_htmp[idx] = htv;
                sht[d*256 + 128 + px] = htv;
            }
        }
    }
    __syncthreads();

    const float L2E = 1.44269504f;
    #pragma unroll
    for (int p = 0; p < 2; p++) {
        int n = p ? n1 : n0;
        int sx = p*128 + px;
        size_t pb = (size_t)b*D*NPIX + n;
        if (grp == 0) {
            float ht[D];
            #pragma unroll
            for (int d = 0; d < D; d++) ht[d] = sht[d*256 + sx];
            #pragma unroll
            for (int o = 0; o < D; o++) {
                float q = 0.f, kh = 0.f;
                #pragma unroll
                for (int d = 0; d < D; d++) {
                    q  = fmaf(spw[      o*13 + d], ht[d], q);
                    kh = fmaf(spw[169 + o*13 + d], ht[d], kh);
                }
                g_q [pb + (size_t)o*NPIX] = q*L2E;
                g_kh[pb + (size_t)o*NPIX] = kh;
            }
        } else {
            float ht[D], mv[D];
            #pragma unroll
            for (int d = 0; d < D; d++) {
                ht[d] = sht[d*256 + sx];
                mv[d] = g_m[((size_t)b*D + d)*NPIX + n];
            }
            #pragma unroll
            for (int o = 0; o < D; o++) {
                float vh = 0.f, km = 0.f, vm = 0.f;
                #pragma unroll
                for (int d = 0; d < D; d++) {
                    vh = fmaf(spw[338 + o*13 + d], ht[d], vh);
                    km = fmaf(spw[507 + o*13 + d], mv[d], km);
                    vm = fmaf(spw[676 + o*13 + d], mv[d], vm);
                }
                g_vh[pb + (size_t)o*NPIX] = vh;
                g_km[pb + (size_t)o*NPIX] = km;
                g_vm[pb + (size_t)o*NPIX] = vm;
            }
        }
    }
}

// ---------------- warp-MMA flash attention: q4-outer loop (fragments loaded once) ----------------
#define KSTR 24
#define VSTR 136
#define VROWS 16
#define BUFH (2*128*KSTR + VROWS*VSTR)
#define OFF_KLO (128*KSTR)
#define OFF_V   (2*128*KSTR)

__global__ void __launch_bounds__(256, 2) sam_attn_mma() {
    __shared__ unsigned short smb[2*BUFH];

    int tid = threadIdx.x;
    int w    = tid >> 5;
    int lane = tid & 31;
    int g = lane >> 2, t = lane & 3;
    int grp = lane >> 3, rr = lane & 7;

    int qt  = blockIdx.x;
    int b   = blockIdx.y;
    int att = blockIdx.z;

    const float* Qp = g_q + (size_t)b*D*NPIX;
    const float* Kp = (att ? g_km : g_kh) + (size_t)b*D*NPIX;
    const float* Vp = (att ? g_vm : g_vh) + (size_t)b*D*NPIX;

    for (int i = tid; i < 2*BUFH; i += 256) smb[i] = 0;
    __syncthreads();
    if (tid < 128) {
        smb[OFF_V + 13*VSTR + tid]        = 0x3F80;
        smb[BUFH + OFF_V + 13*VSTR + tid] = 0x3F80;
    }

    uint32_t SMB = smem_u32(smb);

    int Q0 = qt*256 + w*32;
    uint32_t ah[2][4];
    #pragma unroll
    for (int m = 0; m < 2; m++) {
        int r0 = Q0 + m*16 + g;
        #pragma unroll
        for (int k = 0; k < 2; k++) {
            int dd0 = 2*t + k*8, dd1 = dd0 + 1;
            float q00 = (dd0 < 13) ? Qp[(size_t)dd0*NPIX + r0]     : 0.f;
            float q01 = (dd1 < 13) ? Qp[(size_t)dd1*NPIX + r0]     : 0.f;
            float q10 = (dd0 < 13) ? Qp[(size_t)dd0*NPIX + r0 + 8] : 0.f;
            float q11 = (dd1 < 13) ? Qp[(size_t)dd1*NPIX + r0 + 8] : 0.f;
            ah[m][2*k]   = (uint32_t)bf16of(q00) | ((uint32_t)bf16of(q01) << 16);
            ah[m][2*k+1] = (uint32_t)bf16of(q10) | ((uint32_t)bf16of(q11) << 16);
        }
    }

    float z[2][2][4];
    #pragma unroll
    for (int m = 0; m < 2; m++)
        #pragma unroll
        for (int nt = 0; nt < 2; nt++)
            #pragma unroll
            for (int i = 0; i < 4; i++) z[m][nt][i] = 0.f;

    float kreg[7], vreg[7];
    #pragma unroll
    for (int j = 0; j < 7; j++) {
        int i = tid + 256*j;
        if (i < 1664) {
            int dd = i >> 7, key = i & 127;
            kreg[j] = Kp[(size_t)dd*NPIX + key];
            vreg[j] = Vp[(size_t)dd*NPIX + key];
        }
    }
    {
        unsigned short* bK = smb;
        unsigned short* bV = smb + OFF_V;
        #pragma unroll
        for (int j = 0; j < 7; j++) {
            int i = tid + 256*j;
            if (i < 1664) {
                int dd = i >> 7, key = i & 127;
                unsigned short h, l;
                bfsplit(kreg[j], h, l);
                bK[key*KSTR + dd]           = h;
                bK[OFF_KLO + key*KSTR + dd] = l;
                bV[dd*VSTR + key] = bf16of(vreg[j]);
            }
        }
    }
    __syncthreads();

    for (int kt = 0; kt < NKT; kt++) {
        if (kt + 1 < NKT) {
            #pragma unroll
            for (int j = 0; j < 7; j++) {
                int i = tid + 256*j;
                if (i < 1664) {
                    int dd = i >> 7, key = i & 127;
                    kreg[j] = Kp[(size_t)dd*NPIX + (kt+1)*128 + key];
                    vreg[j] = Vp[(size_t)dd*NPIX + (kt+1)*128 + key];
                }
            }
        }

        uint32_t base = SMB + (uint32_t)(kt & 1)*BUFH*2;
        uint32_t KHI = base;
        uint32_t KLO = base + OFF_KLO*2;
        uint32_t VB  = base + OFF_V*2;

        // q4 OUTER: K/V fragments loaded once, used for both m-tiles
        #pragma unroll
        for (int q4 = 0; q4 < 4; q4++) {
            uint32_t bh[8], bl[8];
            int nt_a = q4*4 + (grp >> 1);
            int nt_b = nt_a + 2;
            uint32_t offa = (uint32_t)((nt_a*8 + rr)*48 + (grp & 1)*16);
            uint32_t offb = (uint32_t)((nt_b*8 + rr)*48 + (grp & 1)*16);
            LDM_X4(bh,     KHI + offa);
            LDM_X4(bh + 4, KHI + offb);
            LDM_X4(bl,     KLO + offa);
            LDM_X4(bl + 4, KLO + offb);

            uint32_t pa[2][8];
            #pragma unroll
            for (int m = 0; m < 2; m++) {
                float s[4][4];
                #pragma unroll
                for (int nt = 0; nt < 4; nt++) {
                    #pragma unroll
                    for (int i = 0; i < 4; i++) s[nt][i] = 0.f;
                    MMA_BF16(s[nt], ah[m], &bh[nt*2]);
                    MMA_BF16(s[nt], ah[m], &bl[nt*2]);
                }
                #pragma unroll
                for (int j = 0; j < 2; j++) {
                    pa[m][j*4+0] = bf16pair(ex2f(s[2*j][0]),   ex2f(s[2*j][1]));
                    pa[m][j*4+1] = bf16pair(ex2f(s[2*j][2]),   ex2f(s[2*j][3]));
                    pa[m][j*4+2] = bf16pair(ex2f(s[2*j+1][0]), ex2f(s[2*j+1][1]));
                    pa[m][j*4+3] = bf16pair(ex2f(s[2*j+1][2]), ex2f(s[2*j+1][3]));
                }
            }

            #pragma unroll
            for (int nt2 = 0; nt2 < 2; nt2++) {
                uint32_t vb[4];
                uint32_t av = VB + (uint32_t)((nt2*8 + rr)*(VSTR*2)
                            + (16*(q4*2 + (grp >> 1)) + 8*(grp & 1))*2);
                LDM_X4(vb, av);
                MMA_BF16(z[0][nt2], pa[0],     vb);
                MMA_BF16(z[0][nt2], pa[0] + 4, vb + 2);
                MMA_BF16(z[1][nt2], pa[1],     vb);
                MMA_BF16(z[1][nt2], pa[1] + 4, vb + 2);
            }
        }

        if (kt + 1 < NKT) {
            unsigned short* bK = smb + ((kt + 1) & 1)*BUFH;
            unsigned short* bV = bK + OFF_V;
            #pragma unroll
            for (int j = 0; j < 7; j++) {
                int i = tid + 256*j;
                if (i < 1664) {
                    int dd = i >> 7, key = i & 127;
                    unsigned short h, l;
                    bfsplit(kreg[j], h, l);
                    bK[key*KSTR + dd]           = h;
                    bK[OFF_KLO + key*KSTR + dd] = l;
                    bV[dd*VSTR + key] = bf16of(vreg[j]);
                }
            }
            __syncthreads();
        }
    }

    float* ob = g_part + (size_t)(att*BATCH + b)*14*NPIX;
    #pragma unroll
    for (int m = 0; m < 2; m++) {
        int r0 = Q0 + m*16 + g;
        #pragma unroll
        for (int nt = 0; nt < 2; nt++) {
            int dd0 = nt*8 + 2*t, dd1 = dd0 + 1;
            if (dd0 < 14) {
                ob[(size_t)dd0*NPIX + r0]     = z[m][nt][0];
                ob[(size_t)dd0*NPIX + r0 + 8] = z[m][nt][2];
            }
            if (dd1 < 14) {
                ob[(size_t)dd1*NPIX + r0]     = z[m][nt][1];
                ob[(size_t)dd1*NPIX + r0 + 8] = z[m][nt][3];
            }
        }
    }
}

// ---------------- SAM fuse + state update ----------------
__global__ void __launch_bounds__(256) sam_post(
        const float* __restrict__ Wz, const float* __restrict__ Wm) {
    __shared__ float swz[13*26], swm[39*26];
    for (int i = threadIdx.x; i < 13*26; i += 256) swz[i] = Wz[i];
    for (int i = threadIdx.x; i < 39*26; i += 256) swm[i] = Wm[i];
    __syncthreads();
    int g = blockIdx.x*256 + threadIdx.x;
    int b = g >> 10, n = g & 1023;

    const float* ph = g_part + ((size_t)b*14)*NPIX + n;
    const float* pm = g_part + ((size_t)(BATCH + b)*14)*NPIX + n;
    float invH = 1.f/ph[(size_t)13*NPIX];
    float invM = 1.f/pm[(size_t)13*NPIX];

    float zh[D], zm[D], hf[D], mf[D];
    #pragma unroll
    for (int d = 0; d < D; d++) {
        zh[d] = ph[(size_t)d*NPIX]*invH;
        zm[d] = pm[(size_t)d*NPIX]*invM;
        size_t idx = ((size_t)b*D + d)*NPIX + n;
        hf[d] = g_htmp[idx]; mf[d] = g_m[idx];
    }
    float Z[D];
    #pragma unroll
    for (int o = 0; o < D; o++) {
        float a = 0.f;
        #pragma unroll
        for (int c = 0; c < D; c++) {
            a = fmaf(swz[o*26 + c],      zh[c], a);
            a = fmaf(swz[o*26 + 13 + c], zm[c], a);
        }
        Z[o] = a;
    }
    #pragma unroll
    for (int o = 0; o < D; o++) {
        float ao = 0.f, ag = 0.f, ai = 0.f;
        #pragma unroll
        for (int c = 0; c < D; c++) {
            ao = fmaf(swm[(     o)*26 + c], Z[c], ao); ao = fmaf(swm[(     o)*26 + 13 + c], hf[c], ao);
            ag = fmaf(swm[(13 + o)*26 + c], Z[c], ag); ag = fmaf(swm[(13 + o)*26 + 13 + c], hf[c], ag);
            ai = fmaf(swm[(26 + o)*26 + c], Z[c], ai); ai = fmaf(swm[(26 + o)*26 + 13 + c], hf[c], ai);
        }
        float mi = 1.f/(1.f + __expf(-ai));
        float mn = (1.f - mi)*mf[o] + mi*tanhf(ag);
        size_t idx = ((size_t)b*D + o)*NPIX + n;
        g_m[idx] = mn;
        g_h[idx] = mn/(1.f + __expf(-ao));
    }
}

// ---------------- final 1x1 conv + log_softmax ----------------
__global__ void __launch_bounds__(256) final_logsoftmax(
        const float* __restrict__ Wf, const float* __restrict__ bf,
        float* __restrict__ out) {
    __shared__ float sw[NCL*D], sb2[NCL];
    for (int i = threadIdx.x; i < NCL*D; i += 256) sw[i] = Wf[i];
    if (threadIdx.x < NCL) sb2[threadIdx.x] = bf[threadIdx.x];
    __syncthreads();
    int g = blockIdx.x*256 + threadIdx.x;
    int b = g >> 10, n = g & 1023;
    float cv[D];
    #pragma unroll
    for (int d = 0; d < D; d++) cv[d] = g_c[((size_t)b*D + d)*NPIX + n];
    float l[NCL]; float mx = -INFINITY;
    #pragma unroll
    for (int o = 0; o < NCL; o++) {
        float a = sb2[o];
        #pragma unroll
        for (int d = 0; d < D; d++) a = fmaf(sw[o*13 + d], cv[d], a);
        l[o] = a; mx = fmaxf(mx, a);
    }
    float sum = 0.f;
    #pragma unroll
    for (int o = 0; o < NCL; o++) sum += __expf(l[o] - mx);
    float lse = mx + logf(sum);
    #pragma unroll
    for (int o = 0; o < NCL; o++)
        out[((size_t)b*NCL + o)*NPIX + n] = l[o] - lse;
}

// ---------------- launch ----------------
extern "C" void kernel_launch(void* const* d_in, const int* in_sizes, int n_in,
                              void* d_out, int out_size) {
    const float* x1  = (const float*)d_in[0];
    const float* Wg  = (const float*)d_in[1];
    const float* Wq  = (const float*)d_in[2];
    const float* Wkh = (const float*)d_in[3];
    const float* Wvh = (const float*)d_in[4];
    const float* Wkm = (const float*)d_in[5];
    const float* Wvm = (const float*)d_in[6];
    const float* Wz  = (const float*)d_in[7];
    const float* Wm  = (const float*)d_in[8];
    const float* Wf  = (const float*)d_in[9];
    const float* bf  = (const float*)d_in[10];
    float* out = (float*)d_out;

    cudaFuncSetAttribute(conv_lstm_proj, cudaFuncAttributeMaxDynamicSharedMemorySize, CONV_SMEM6);

    zero_state<<<256, 256>>>();
    pack_conv_weights<<<(CONV_WP + 255)/256, 256>>>(Wg);
    for (int t = 0; t < TSTEPS; t++) {
        conv_lstm_proj<<<dim3(4, BATCH), 256, CONV_SMEM6>>>(x1, t, Wq, Wkh, Wvh, Wkm, Wvm);
        // step 23's SAM (attention + post) only affects h/m, which are never
        // consumed — the output depends solely on c. Skip them.
        if (t < TSTEPS - 1) {
            sam_attn_mma<<<dim3(4, BATCH, 2), 256>>>();
            sam_post<<<128, 256>>>(Wz, Wm);
        }
    }
    final_logsoftmax<<<128, 256>>>(Wf, bf, out);
}